// round 7
// baseline (speedup 1.0000x reference)
#include <cuda_runtime.h>
#include <cstdint>

// FHE BSGS rotate/mul/accumulate. Fixed shapes: x[64,65536] f32, diag[16,65536] f32,
// stride=1, reps=1 -> out[b,s] = sum_t x[b,(s2+2^t)&65535] * diag[t,s2], s2 = s^32768.
// Quad space (float4): s2-quad = Sq ^ 8192; shift 2^t slots = 2^(t-2) quads for t>=2.
#define SLOTS 65536
#define SQ    (SLOTS / 4)      // 16384 quads per row
#define QM    (SQ - 1)
#define BATCH 64
#define BPC   8                // batches per CTA
#define TPB   512              // 256 lo-threads (t=0..7) + 256 hi-threads (t=8..15)

typedef unsigned long long u64;

__device__ __forceinline__ u64 fma2(u64 x, u64 d, u64 a) {
    u64 r; asm("fma.rn.f32x2 %0, %1, %2, %3;" : "=l"(r) : "l"(x), "l"(d), "l"(a)); return r;
}
__device__ __forceinline__ u64 mul2(u64 x, u64 d) {
    u64 r; asm("mul.rn.f32x2 %0, %1, %2;" : "=l"(r) : "l"(x), "l"(d)); return r;
}
__device__ __forceinline__ u64 add2(u64 x, u64 y) {
    u64 r; asm("add.rn.f32x2 %0, %1, %2;" : "=l"(r) : "l"(x), "l"(y)); return r;
}
__device__ __forceinline__ u64 pack2(float lo, float hi) {
    u64 r; asm("mov.b64 %0, {%1, %2};" : "=l"(r) : "f"(lo), "f"(hi)); return r;
}

__global__ __launch_bounds__(TPB, 2)
void fhe_bsgs_ws(const float* __restrict__ x,
                 const float* __restrict__ diag,
                 float* __restrict__ out)
{
    __shared__ ulonglong2 part[2][256];   // hi-half partials, double buffered (8 KB)

    const int tid = threadIdx.x;
    const int lq  = tid & 255;                  // local output quad
    const int Sq  = blockIdx.x * 256 + lq;      // global output quad
    const int q2  = Sq ^ 8192;                  // rolled (s2-space) quad
    const int b0  = blockIdx.y * BPC;

    const float4*     x4 = reinterpret_cast<const float4*>(x);
    const ulonglong2* x8 = reinterpret_cast<const ulonglong2*>(x);
    const float4*     d4 = reinterpret_cast<const float4*>(diag);
    const ulonglong2* d8 = reinterpret_cast<const ulonglong2*>(diag);

    if (tid >= 256) {
        // ---- hi half: t = 8..15 (shifts 256..32768 slots = 64..8192 quads) ----
        ulonglong2 dvp[8];
        #pragma unroll
        for (int t = 0; t < 8; t++)
            dvp[t] = d8[(t + 8) * SQ + q2];

        unsigned qh[8];
        #pragma unroll
        for (int g = 0; g < 8; g++)
            qh[g] = (unsigned)(q2 + (64 << g)) & QM;

        #pragma unroll 1
        for (int i = 0; i < BPC; i++) {
            const ulonglong2* __restrict__ xr = x8 + (size_t)(b0 + i) * SQ;

            const ulonglong2 X0 = xr[qh[0]];
            const ulonglong2 X1 = xr[qh[1]];
            const ulonglong2 X2 = xr[qh[2]];
            const ulonglong2 X3 = xr[qh[3]];
            const ulonglong2 X4 = xr[qh[4]];
            const ulonglong2 X5 = xr[qh[5]];
            const ulonglong2 X6 = xr[qh[6]];
            const ulonglong2 X7 = xr[qh[7]];

            u64 alo = mul2(X0.x, dvp[0].x);
            u64 ahi = mul2(X0.y, dvp[0].y);
            alo = fma2(X1.x, dvp[1].x, alo);  ahi = fma2(X1.y, dvp[1].y, ahi);
            alo = fma2(X2.x, dvp[2].x, alo);  ahi = fma2(X2.y, dvp[2].y, ahi);
            alo = fma2(X3.x, dvp[3].x, alo);  ahi = fma2(X3.y, dvp[3].y, ahi);
            alo = fma2(X4.x, dvp[4].x, alo);  ahi = fma2(X4.y, dvp[4].y, ahi);
            alo = fma2(X5.x, dvp[5].x, alo);  ahi = fma2(X5.y, dvp[5].y, ahi);
            alo = fma2(X6.x, dvp[6].x, alo);  ahi = fma2(X6.y, dvp[6].y, ahi);
            alo = fma2(X7.x, dvp[7].x, alo);  ahi = fma2(X7.y, dvp[7].y, ahi);

            part[i & 1][lq] = make_ulonglong2(alo, ahi);
            __syncthreads();
        }
    } else {
        // ---- lo half: t = 0..7 (shifts 1..128 slots) ----
        float4 dvs[3];                         // t=0..2 (misaligned windows)
        #pragma unroll
        for (int t = 0; t < 3; t++)
            dvs[t] = d4[t * SQ + q2];
        ulonglong2 dvp[5];                     // t=3..7 (aligned, packed)
        #pragma unroll
        for (int t = 3; t < 8; t++)
            dvp[t - 3] = d8[t * SQ + q2];

        const unsigned qA = (unsigned)q2;
        const unsigned qB = (unsigned)(q2 + 1) & QM;
        unsigned ql[5];                        // shifts 8..128 slots = 2..32 quads
        #pragma unroll
        for (int g = 0; g < 5; g++)
            ql[g] = (unsigned)(q2 + (2 << g)) & QM;

        ulonglong2* __restrict__ o8 = reinterpret_cast<ulonglong2*>(out);

        #pragma unroll 1
        for (int i = 0; i < BPC; i++) {
            const float4*     __restrict__ xr4 = x4 + (size_t)(b0 + i) * SQ;
            const ulonglong2* __restrict__ xr8 = x8 + (size_t)(b0 + i) * SQ;

            const float4 A  = xr4[qA];
            const float4 Bv = xr4[qB];
            const ulonglong2 X3 = xr8[ql[0]];
            const ulonglong2 X4 = xr8[ql[1]];
            const ulonglong2 X5 = xr8[ql[2]];
            const ulonglong2 X6 = xr8[ql[3]];
            const ulonglong2 X7 = xr8[ql[4]];

            // t=0..2 scalar
            float s0, s1, s2, s3;
            s0 = A.y  * dvs[0].x;               // t=0: (A.y,A.z,A.w,B.x)
            s1 = A.z  * dvs[0].y;
            s2 = A.w  * dvs[0].z;
            s3 = Bv.x * dvs[0].w;
            s0 = fmaf(A.z,  dvs[1].x, s0);      // t=1: (A.z,A.w,B.x,B.y)
            s1 = fmaf(A.w,  dvs[1].y, s1);
            s2 = fmaf(Bv.x, dvs[1].z, s2);
            s3 = fmaf(Bv.y, dvs[1].w, s3);
            s0 = fmaf(Bv.x, dvs[2].x, s0);      // t=2: B
            s1 = fmaf(Bv.y, dvs[2].y, s1);
            s2 = fmaf(Bv.z, dvs[2].z, s2);
            s3 = fmaf(Bv.w, dvs[2].w, s3);

            u64 alo = pack2(s0, s1);
            u64 ahi = pack2(s2, s3);
            alo = fma2(X3.x, dvp[0].x, alo);  ahi = fma2(X3.y, dvp[0].y, ahi);
            alo = fma2(X4.x, dvp[1].x, alo);  ahi = fma2(X4.y, dvp[1].y, ahi);
            alo = fma2(X5.x, dvp[2].x, alo);  ahi = fma2(X5.y, dvp[2].y, ahi);
            alo = fma2(X6.x, dvp[3].x, alo);  ahi = fma2(X6.y, dvp[3].y, ahi);
            alo = fma2(X7.x, dvp[4].x, alo);  ahi = fma2(X7.y, dvp[4].y, ahi);

            __syncthreads();                    // hi partial for batch i is ready
            const ulonglong2 p = part[i & 1][lq];
            alo = add2(alo, p.x);
            ahi = add2(ahi, p.y);

            o8[(size_t)(b0 + i) * SQ + Sq] = make_ulonglong2(alo, ahi);
        }
    }
}

extern "C" void kernel_launch(void* const* d_in, const int* in_sizes, int n_in,
                              void* d_out, int out_size)
{
    const float* x    = (const float*)d_in[0];
    const float* diag = (const float*)d_in[1];
    float* out = (float*)d_out;

    dim3 grid(SQ / 256, BATCH / BPC);   // (64 tiles, 8 batch-groups) = 512 CTAs
    fhe_bsgs_ws<<<grid, TPB>>>(x, diag, out);
}

// round 8
// speedup vs baseline: 1.0718x; 1.0718x over previous
#include <cuda_runtime.h>
#include <cstdint>

// FHE BSGS rotate/mul/accumulate. Fixed shapes: x[64,65536] f32, diag[16,65536] f32,
// stride=1, reps=1 -> out[b,s] = sum_t x[b,(s2+2^t)&65535] * diag[t,s2], s2 = s^32768.
#define SLOTS   65536
#define SQ      (SLOTS / 4)       // 16384 quads per row
#define QM      (SQ - 1)
#define BATCH   64
#define BPC     8                 // batches per CTA
#define TPB     256               // 1 output quad per thread -> 1024-slot tile
#define NEARQ   768               // near-union quads (shifts 1..2048 slots + B quad)
#define NBUF    4                 // 4 buffers -> stage distance 2, 1 barrier/iter

typedef unsigned long long u64;

__device__ __forceinline__ void cpasync16(uint32_t saddr, const float4* g) {
    asm volatile("cp.async.cg.shared.global [%0], [%1], 16;\n" :: "r"(saddr), "l"(g));
}
__device__ __forceinline__ void cp_commit() { asm volatile("cp.async.commit_group;\n"); }
__device__ __forceinline__ void cp_wait2()  { asm volatile("cp.async.wait_group 2;\n"); }
__device__ __forceinline__ void cp_wait1()  { asm volatile("cp.async.wait_group 1;\n"); }
__device__ __forceinline__ void cp_wait0()  { asm volatile("cp.async.wait_group 0;\n"); }

__device__ __forceinline__ u64 fma2(u64 x, u64 d, u64 a) {
    u64 r; asm("fma.rn.f32x2 %0, %1, %2, %3;" : "=l"(r) : "l"(x), "l"(d), "l"(a)); return r;
}
__device__ __forceinline__ u64 mul2(u64 x, u64 d) {
    u64 r; asm("mul.rn.f32x2 %0, %1, %2;" : "=l"(r) : "l"(x), "l"(d)); return r;
}
__device__ __forceinline__ u64 add2(u64 x, u64 y) {
    u64 r; asm("add.rn.f32x2 %0, %1, %2;" : "=l"(r) : "l"(x), "l"(y)); return r;
}
__device__ __forceinline__ u64 pack2(float lo, float hi) {
    u64 r; asm("mov.b64 %0, {%1, %2};" : "=l"(r) : "f"(lo), "f"(hi)); return r;
}

__global__ __launch_bounds__(TPB, 2)
void fhe_bsgs_p4(const float* __restrict__ x,
                 const float* __restrict__ diag,
                 float* __restrict__ out)
{
    __shared__ float4 sbuf[NBUF * NEARQ];   // 49152 B

    const int tid = threadIdx.x;
    const int Sq  = blockIdx.x * TPB;          // output quad base
    const int Tq  = Sq ^ 8192;                 // rolled (s2-space) quad base
    const int b0  = blockIdx.y * BPC;

    const float4* __restrict__ x4 = reinterpret_cast<const float4*>(x);

    // Batch-invariant diag quads. t=0..2 as float4 (misaligned windows), t=3..15 packed.
    const int q2 = Tq + tid;
    float4 dvs[3];
    #pragma unroll
    for (int t = 0; t < 3; t++)
        dvs[t] = reinterpret_cast<const float4*>(diag)[t * SQ + q2];
    ulonglong2 dvp[13];
    #pragma unroll
    for (int t = 3; t < 16; t++)
        dvp[t - 3] = reinterpret_cast<const ulonglong2*>(diag)[t * SQ + q2];

    const uint32_t sb0 = (uint32_t)__cvta_generic_to_shared(sbuf);

    // Far quad indices (shifts 4096..32768 slots -> 1024..8192 quads), coalesced LDG.
    unsigned qf[4];
    #pragma unroll
    for (int g = 0; g < 4; g++)
        qf[g] = (unsigned)(Tq + (1024 << g) + tid) & QM;

    // Stage near union [Tq, Tq+768) for batch b into buffer `buf`.
    auto stage_near = [&](int buf, int b) {
        const float4* __restrict__ xb = x4 + (size_t)b * SQ;
        const uint32_t sb = sb0 + (uint32_t)buf * (NEARQ * 16);
        #pragma unroll
        for (int r = 0; r < 3; r++) {
            const int k = tid + 256 * r;
            cpasync16(sb + k * 16, xb + ((Tq + k) & QM));
        }
        cp_commit();
    };

    // Prologue: two stages in flight; far loads for batch 0.
    stage_near(0, b0);
    stage_near(1, b0 + 1);
    ulonglong2 F[4];
    {
        const ulonglong2* __restrict__ xb =
            reinterpret_cast<const ulonglong2*>(x) + (size_t)b0 * SQ;
        #pragma unroll
        for (int g = 0; g < 4; g++) F[g] = xb[qf[g]];
    }

    #pragma unroll 1
    for (int j = 0; j < BPC; j++) {
        // Stage distance 2: writes buf (j+2)%4; slowest warp reads buf (j-1)%4 -> safe.
        if (j + 2 < BPC) {
            stage_near((j + 2) & (NBUF - 1), b0 + j + 2);
            cp_wait2();                 // group j complete; j+1, j+2 in flight
        } else if (j + 1 < BPC) {
            cp_wait1();
        } else {
            cp_wait0();
        }

        // Next batch's far LDGs: issued now, consumed next iteration.
        ulonglong2 G[4];
        if (j + 1 < BPC) {
            const ulonglong2* __restrict__ xn =
                reinterpret_cast<const ulonglong2*>(x) + (size_t)(b0 + j + 1) * SQ;
            #pragma unroll
            for (int g = 0; g < 4; g++) G[g] = xn[qf[g]];
        }

        __syncthreads();                // publish group j to all threads

        const float4* __restrict__ buf = sbuf + (j & (NBUF - 1)) * NEARQ;
        const ulonglong2* __restrict__ buf64 = reinterpret_cast<const ulonglong2*>(buf);

        const float4 A  = buf[tid];
        const float4 Bv = buf[tid + 1];

        // t=0..2 scalar (misaligned windows)
        float s0, s1, s2, s3;
        s0 = A.y  * dvs[0].x;               // t=0: (A.y,A.z,A.w,B.x)
        s1 = A.z  * dvs[0].y;
        s2 = A.w  * dvs[0].z;
        s3 = Bv.x * dvs[0].w;
        s0 = fmaf(A.z,  dvs[1].x, s0);      // t=1: (A.z,A.w,B.x,B.y)
        s1 = fmaf(A.w,  dvs[1].y, s1);
        s2 = fmaf(Bv.x, dvs[1].z, s2);
        s3 = fmaf(Bv.y, dvs[1].w, s3);
        s0 = fmaf(Bv.x, dvs[2].x, s0);      // t=2: B
        s1 = fmaf(Bv.y, dvs[2].y, s1);
        s2 = fmaf(Bv.z, dvs[2].z, s2);
        s3 = fmaf(Bv.w, dvs[2].w, s3);

        // Chain 1 (t=0..7): packed, seeded from scalar partials.
        u64 a1lo = pack2(s0, s1);
        u64 a1hi = pack2(s2, s3);

        #define ACCP(CLO, CHI, T, IDX) do {                 \
            const ulonglong2 X = buf64[(IDX)];              \
            CLO = fma2(X.x, dvp[(T) - 3].x, CLO);           \
            CHI = fma2(X.y, dvp[(T) - 3].y, CHI);           \
        } while (0)

        ACCP(a1lo, a1hi, 3, tid + 2);
        ACCP(a1lo, a1hi, 4, tid + 4);
        ACCP(a1lo, a1hi, 5, tid + 8);
        ACCP(a1lo, a1hi, 6, tid + 16);
        ACCP(a1lo, a1hi, 7, tid + 32);

        // Chain 2 (t=8..15): packed.
        u64 a2lo, a2hi;
        {
            const ulonglong2 X = buf64[tid + 64];           // t=8
            a2lo = mul2(X.x, dvp[5].x);
            a2hi = mul2(X.y, dvp[5].y);
        }
        ACCP(a2lo, a2hi,  9, tid + 128);
        ACCP(a2lo, a2hi, 10, tid + 256);
        ACCP(a2lo, a2hi, 11, tid + 512);
        #undef ACCP

        // Far shifts t=12..15 from prefetched registers.
        #pragma unroll
        for (int g = 0; g < 4; g++) {
            a2lo = fma2(F[g].x, dvp[9 + g].x, a2lo);
            a2hi = fma2(F[g].y, dvp[9 + g].y, a2hi);
        }

        ulonglong2 acc;
        acc.x = add2(a1lo, a2lo);
        acc.y = add2(a1hi, a2hi);

        reinterpret_cast<ulonglong2*>(out)[(size_t)(b0 + j) * SQ + Sq + tid] = acc;

        #pragma unroll
        for (int g = 0; g < 4; g++) F[g] = G[g];
    }
}

extern "C" void kernel_launch(void* const* d_in, const int* in_sizes, int n_in,
                              void* d_out, int out_size)
{
    const float* x    = (const float*)d_in[0];
    const float* diag = (const float*)d_in[1];
    float* out = (float*)d_out;

    dim3 grid(SQ / TPB, BATCH / BPC);   // (64 tiles, 8 batch-groups) = 512 CTAs
    fhe_bsgs_p4<<<grid, TPB>>>(x, diag, out);
}

// round 9
// speedup vs baseline: 1.0845x; 1.0118x over previous
#include <cuda_runtime.h>
#include <cstdint>

// FHE BSGS rotate/mul/accumulate. Fixed shapes: x[64,65536] f32, diag[16,65536] f32,
// stride=1, reps=1 -> out[b,s] = sum_t x[b,(s2+2^t)&65535] * diag[t,s2], s2 = s^32768.
#define SLOTS   65536
#define SQ      (SLOTS / 4)     // 16384 quads per row
#define QM      (SQ - 1)
#define BATCH   64
#define BPC     8               // batches per CTA
#define TPB     256             // 2 groups x 128 threads; tile 256 quads/CTA
#define GRP     128
#define NEARQ_G 640             // near union per group: 128 tile + 512 reach (incl. B quad)
#define FARQ_G  512             // 4 far windows x 128 quads
#define BUFQ    (NEARQ_G + FARQ_G)            // 1152 quads per group buffer
#define SMEM_BYTES (2 * 2 * BUFQ * 16)        // 2 groups x 2 buffers = 73728 B

typedef unsigned long long u64;

__device__ __forceinline__ void cpasync16(uint32_t saddr, const float4* g) {
    asm volatile("cp.async.cg.shared.global [%0], [%1], 16;\n" :: "r"(saddr), "l"(g));
}
__device__ __forceinline__ void cp_commit() { asm volatile("cp.async.commit_group;\n"); }
__device__ __forceinline__ void cp_wait1()  { asm volatile("cp.async.wait_group 1;\n"); }
__device__ __forceinline__ void cp_wait0()  { asm volatile("cp.async.wait_group 0;\n"); }
__device__ __forceinline__ void gbar(int id) {
    asm volatile("bar.sync %0, %1;" :: "r"(id), "r"(GRP) : "memory");
}

__device__ __forceinline__ u64 fma2(u64 x, u64 d, u64 a) {
    u64 r; asm("fma.rn.f32x2 %0, %1, %2, %3;" : "=l"(r) : "l"(x), "l"(d), "l"(a)); return r;
}
__device__ __forceinline__ u64 mul2(u64 x, u64 d) {
    u64 r; asm("mul.rn.f32x2 %0, %1, %2;" : "=l"(r) : "l"(x), "l"(d)); return r;
}
__device__ __forceinline__ u64 add2(u64 x, u64 y) {
    u64 r; asm("add.rn.f32x2 %0, %1, %2;" : "=l"(r) : "l"(x), "l"(y)); return r;
}
__device__ __forceinline__ u64 pack2(float lo, float hi) {
    u64 r; asm("mov.b64 %0, {%1, %2};" : "=l"(r) : "f"(lo), "f"(hi)); return r;
}

__global__ __launch_bounds__(TPB, 2)
void fhe_bsgs_dp(const float* __restrict__ x,
                 const float* __restrict__ diag,
                 float* __restrict__ out)
{
    extern __shared__ float4 sbuf[];   // [2 groups][2 buffers][BUFQ]

    const int tid = threadIdx.x;
    const int g   = tid >> 7;                  // group 0 / 1
    const int lq  = tid & (GRP - 1);           // lane-in-group = local output quad
    const int Sq  = blockIdx.x * TPB;          // CTA output quad base (256-aligned)
    const int Tg  = (Sq ^ 8192) + g * GRP;     // group's s2-space quad base
    const int b0  = blockIdx.y * BPC;

    const float4* __restrict__ x4 = reinterpret_cast<const float4*>(x);

    // Batch-invariant diag for this thread's output quad (q2 = Tg + lq).
    const int q2 = Tg + lq;
    float4 dvs[3];
    #pragma unroll
    for (int t = 0; t < 3; t++)
        dvs[t] = reinterpret_cast<const float4*>(diag)[t * SQ + q2];
    ulonglong2 dvp[13];
    #pragma unroll
    for (int t = 3; t < 16; t++)
        dvp[t - 3] = reinterpret_cast<const ulonglong2*>(diag)[t * SQ + q2];

    float4* const gbase = sbuf + g * (2 * BUFQ);
    const uint32_t gb0 = (uint32_t)__cvta_generic_to_shared(gbase);

    // Stage full union (near 640 + far 512 quads) for batch b into group buffer `buf`.
    auto stage = [&](int buf, int b) {
        const float4* __restrict__ xb = x4 + (size_t)b * SQ;
        const uint32_t sb = gb0 + (uint32_t)buf * (BUFQ * 16);
        #pragma unroll
        for (int r = 0; r < 5; r++) {                      // near: [Tg, Tg+640)
            const int k = lq + GRP * r;
            cpasync16(sb + k * 16, xb + ((Tg + k) & QM));
        }
        #pragma unroll
        for (int w = 0; w < 4; w++) {                      // far windows
            const int k = NEARQ_G + GRP * w + lq;
            cpasync16(sb + k * 16, xb + ((Tg + lq + (1024 << w)) & QM));
        }
        cp_commit();
    };

    stage(0, b0);
    const int barid = 1 + g;

    #pragma unroll 1
    for (int j = 0; j < BPC; j++) {
        if (j + 1 < BPC) {
            stage((j + 1) & 1, b0 + j + 1);   // prefetch next batch (other buffer)
            cp_wait1();
        } else {
            cp_wait0();
        }
        gbar(barid);                           // publish group j data (group-local)

        const float4* __restrict__ near4 = gbase + (j & 1) * BUFQ;
        const ulonglong2* __restrict__ near8 = reinterpret_cast<const ulonglong2*>(near4);
        const ulonglong2* __restrict__ far8  = near8 + NEARQ_G;

        const float4 A  = near4[lq];
        const float4 Bv = near4[lq + 1];

        // t=0..2 scalar (misaligned windows)
        float s0, s1, s2, s3;
        s0 = A.y  * dvs[0].x;               // t=0: (A.y,A.z,A.w,B.x)
        s1 = A.z  * dvs[0].y;
        s2 = A.w  * dvs[0].z;
        s3 = Bv.x * dvs[0].w;
        s0 = fmaf(A.z,  dvs[1].x, s0);      // t=1: (A.z,A.w,B.x,B.y)
        s1 = fmaf(A.w,  dvs[1].y, s1);
        s2 = fmaf(Bv.x, dvs[1].z, s2);
        s3 = fmaf(Bv.y, dvs[1].w, s3);
        s0 = fmaf(Bv.x, dvs[2].x, s0);      // t=2: B
        s1 = fmaf(Bv.y, dvs[2].y, s1);
        s2 = fmaf(Bv.z, dvs[2].z, s2);
        s3 = fmaf(Bv.w, dvs[2].w, s3);

        u64 a1lo = pack2(s0, s1);
        u64 a1hi = pack2(s2, s3);

        #define ACCP(CLO, CHI, T, PTR, IDX) do {            \
            const ulonglong2 X = (PTR)[(IDX)];              \
            CLO = fma2(X.x, dvp[(T) - 3].x, CLO);           \
            CHI = fma2(X.y, dvp[(T) - 3].y, CHI);           \
        } while (0)

        // Chain 1: t=3..7 (shifts 2..32 quads)
        ACCP(a1lo, a1hi, 3, near8, lq + 2);
        ACCP(a1lo, a1hi, 4, near8, lq + 4);
        ACCP(a1lo, a1hi, 5, near8, lq + 8);
        ACCP(a1lo, a1hi, 6, near8, lq + 16);
        ACCP(a1lo, a1hi, 7, near8, lq + 32);

        // Chain 2: t=8..15
        u64 a2lo, a2hi;
        {
            const ulonglong2 X = near8[lq + 64];            // t=8
            a2lo = mul2(X.x, dvp[5].x);
            a2hi = mul2(X.y, dvp[5].y);
        }
        ACCP(a2lo, a2hi,  9, near8, lq + 128);
        ACCP(a2lo, a2hi, 10, near8, lq + 256);
        ACCP(a2lo, a2hi, 11, near8, lq + 512);
        ACCP(a2lo, a2hi, 12, far8, 0 * GRP + lq);           // t=12..15 staged far
        ACCP(a2lo, a2hi, 13, far8, 1 * GRP + lq);
        ACCP(a2lo, a2hi, 14, far8, 2 * GRP + lq);
        ACCP(a2lo, a2hi, 15, far8, 3 * GRP + lq);
        #undef ACCP

        ulonglong2 acc;
        acc.x = add2(a1lo, a2lo);
        acc.y = add2(a1hi, a2hi);

        reinterpret_cast<ulonglong2*>(out)[(size_t)(b0 + j) * SQ + Sq + g * GRP + lq] = acc;

        gbar(barid);   // group reads done before this buffer is restaged
    }
}

extern "C" void kernel_launch(void* const* d_in, const int* in_sizes, int n_in,
                              void* d_out, int out_size)
{
    const float* x    = (const float*)d_in[0];
    const float* diag = (const float*)d_in[1];
    float* out = (float*)d_out;

    static bool attr_set = false;
    if (!attr_set) {
        cudaFuncSetAttribute(fhe_bsgs_dp,
                             cudaFuncAttributeMaxDynamicSharedMemorySize, SMEM_BYTES);
        attr_set = true;
    }

    dim3 grid(SQ / TPB, BATCH / BPC);   // (64 tiles, 8 batch-groups) = 512 CTAs
    fhe_bsgs_dp<<<grid, TPB, SMEM_BYTES>>>(x, diag, out);
}